// round 13
// baseline (speedup 1.0000x reference)
#include <cuda_runtime.h>
#include <cuda_fp16.h>
#include <cstdint>

#define BB 4
#define M_PER_B 65536
#define KS_B 32

// ---- device scratch (static: allocation-free) ----
__device__ float  g_c[BB*256];                      // bq.k_n/16
__device__ __half g_Ah[BB*256*256];                 // A fp16 [b][n][h] (incl 1/16)
__device__ __half g_Sh[(size_t)BB*M_PER_B*256];     // S fp16 (written by passA)
__device__ __half g_Ph[(size_t)BB*256*M_PER_B];     // P^T fp16 [b][n][m]
__device__ float  g_W[(size_t)BB*KS_B*2*128*256];   // split-K partials of G (33.5 MB)
__device__ float  g_Wt[BB*KS_B*2*128];              // split-K partials of t[n]
__device__ float  g_G[BB*256*256];                  // reduced G [b][n][h] (1 MB)
__device__ float  g_T[BB*256];                      // reduced t [b][n]

// ---- helpers ----
__device__ __forceinline__ uint32_t smem_u32(const void* p) {
    return (uint32_t)__cvta_generic_to_shared(p);
}
__device__ __forceinline__ void cp16(uint32_t dst, const void* src) {
    asm volatile("cp.async.cg.shared.global [%0], [%1], 16;" :: "r"(dst), "l"(src));
}
#define CP_COMMIT() asm volatile("cp.async.commit_group;" ::: "memory")
#define CP_WAIT0()  asm volatile("cp.async.wait_group 0;" ::: "memory")

__device__ __forceinline__ uint32_t pack_h2(float lo, float hi) {
    uint32_t r;
    asm("cvt.rn.f16x2.f32 %0, %1, %2;" : "=r"(r) : "f"(hi), "f"(lo));
    return r;
}
__device__ __forceinline__ void ldm_x4(uint32_t* r, uint32_t addr) {
    asm volatile("ldmatrix.sync.aligned.m8n8.x4.shared.b16 {%0,%1,%2,%3}, [%4];"
        : "=r"(r[0]), "=r"(r[1]), "=r"(r[2]), "=r"(r[3]) : "r"(addr));
}
__device__ __forceinline__ void ldm_x4t(uint32_t* r, uint32_t addr) {
    asm volatile("ldmatrix.sync.aligned.m8n8.x4.trans.shared.b16 {%0,%1,%2,%3}, [%4];"
        : "=r"(r[0]), "=r"(r[1]), "=r"(r[2]), "=r"(r[3]) : "r"(addr));
}
__device__ __forceinline__ void mma16(float* d, const uint32_t* a,
                                      uint32_t b0, uint32_t b1) {
    asm volatile("mma.sync.aligned.m16n8k16.row.col.f32.f16.f16.f32 "
        "{%0,%1,%2,%3}, {%4,%5,%6,%7}, {%8,%9}, {%0,%1,%2,%3};"
        : "+f"(d[0]), "+f"(d[1]), "+f"(d[2]), "+f"(d[3])
        : "r"(a[0]), "r"(a[1]), "r"(a[2]), "r"(a[3]), "r"(b0), "r"(b1));
}

// =====================================================================
// Kernel 1: K = hidden@Wk + bk ; A fp16 [b][n][h] = (Wq[h,:].K[b,n,:])/16 ;
//           c[b][n] = (bq . K[b,n,:])/16
// =====================================================================
__global__ void __launch_bounds__(256) prep_kernel(
    const float* __restrict__ hidden,
    const float* __restrict__ Wq, const float* __restrict__ bq,
    const float* __restrict__ Wk, const float* __restrict__ bk)
{
    int n = blockIdx.x, b = blockIdx.y, t = threadIdx.x;
    __shared__ float hrow[256];
    __shared__ float krow[256];
    hrow[t] = hidden[(b*256 + n)*256 + t];
    __syncthreads();

    float a = bk[t];
    #pragma unroll 8
    for (int h = 0; h < 256; h++) a += hrow[h] * Wk[h*256 + t];
    krow[t] = a;
    __syncthreads();

    int lane = t & 31, w = t >> 5;
    const float sc = 0.0625f;
    for (int h = w; h < 256; h += 8) {
        float s = 0.f;
        #pragma unroll 4
        for (int d = lane; d < 256; d += 32) s += Wq[h*256 + d] * krow[d];
        #pragma unroll
        for (int of = 16; of > 0; of >>= 1) s += __shfl_xor_sync(0xffffffffu, s, of);
        if (lane == 0) g_Ah[(b*256 + n)*256 + h] = __float2half(s * sc);
    }
    if (w == 0) {
        float s = 0.f;
        #pragma unroll 4
        for (int d = lane; d < 256; d += 32) s += bq[d] * krow[d];
        #pragma unroll
        for (int of = 16; of > 0; of >>= 1) s += __shfl_xor_sync(0xffffffffu, s, of);
        if (lane == 0) g_c[b*256 + n] = s * sc;
    }
}

// =====================================================================
// passA (round-10 proven config): CTA 64m x 256n, occ 2. fp16 mma +
// ldmatrix. K=256, 8 chunks of 32, double-buffered.
// =====================================================================
__global__ void __launch_bounds__(256, 2) passA_kernel(
    const float* __restrict__ S, const float* __restrict__ am)
{
    extern __shared__ char shc[];
    float* csm  = (float*)(shc + 51200);
    float* rsum = (float*)(shc + 52224);
    const uint32_t base_u = smem_u32(shc);

    const int tid = threadIdx.x, lane = tid & 31, w = tid >> 5;
    const int mg = w >> 1, ng = w & 1;
    const int r = lane >> 2, q = lane & 3;
    const int b = blockIdx.y;
    const int m0 = blockIdx.x * 64;

    csm[tid] = g_c[b*256 + tid];

    const float*  Sb  = S + ((size_t)b*M_PER_B + m0)*256;
    const __half* Abh = g_Ah + b*65536;

    float acc[64];
    #pragma unroll
    for (int i = 0; i < 64; i++) acc[i] = 0.f;

    const int srow = tid >> 2, sseg = tid & 3;
    float4 v0, v1;

    const uint32_t aOff = (uint32_t)(mg*16 + (lane & 15))*80 + (lane >> 4)*16;
    const uint32_t bOff = 5120u + (uint32_t)(ng*128 + (lane & 15))*80 + (lane >> 4)*16;

    // ---- chunk 0 preamble ----
    {
        const float4* sp = (const float4*)(Sb + (size_t)srow*256 + sseg*8);
        v0 = sp[0]; v1 = sp[1];
        uint32_t dst = base_u + 5120;
        #pragma unroll
        for (int i = 0; i < 4; i++) {
            int idx = i*256 + tid;
            int row = idx >> 2, c = idx & 3;
            cp16(dst + (uint32_t)row*80 + c*16, Abh + row*256 + c*8);
        }
        CP_COMMIT();
        uint4 q0 = make_uint4(pack_h2(v0.x, v0.y), pack_h2(v0.z, v0.w),
                              pack_h2(v1.x, v1.y), pack_h2(v1.z, v1.w));
        *(uint4*)(shc + srow*80 + sseg*16) = q0;
        *(uint4*)(g_Sh + ((size_t)b*M_PER_B + m0 + srow)*256 + sseg*8) = q0;
        CP_WAIT0();
        __syncthreads();
    }

    for (int kc = 0; kc < 8; kc++) {
        if (kc < 7) {
            int k0 = (kc + 1)*32;
            const float4* sp = (const float4*)(Sb + (size_t)srow*256 + k0 + sseg*8);
            v0 = sp[0]; v1 = sp[1];
            uint32_t dst = base_u + ((kc + 1) & 1)*25600 + 5120;
            #pragma unroll
            for (int i = 0; i < 4; i++) {
                int idx = i*256 + tid;
                int row = idx >> 2, c = idx & 3;
                cp16(dst + (uint32_t)row*80 + c*16, Abh + row*256 + k0 + c*8);
            }
            CP_COMMIT();
        }
        uint32_t sb = base_u + (kc & 1)*25600;
        #pragma unroll
        for (int step = 0; step < 2; step++) {
            uint32_t af[4];
            ldm_x4(af, sb + aOff + step*32);
            #pragma unroll
            for (int p = 0; p < 8; p++) {
                uint32_t bf[4];
                ldm_x4(bf, sb + bOff + p*1280 + step*32);
                mma16(acc + (p*2)*4,   af, bf[0], bf[2]);
                mma16(acc + (p*2+1)*4, af, bf[1], bf[3]);
            }
        }
        if (kc < 7) {
            int k0 = (kc + 1)*32;
            int stage = (kc + 1) & 1;
            uint4 q0 = make_uint4(pack_h2(v0.x, v0.y), pack_h2(v0.z, v0.w),
                                  pack_h2(v1.x, v1.y), pack_h2(v1.z, v1.w));
            *(uint4*)(shc + stage*25600 + srow*80 + sseg*16) = q0;
            *(uint4*)(g_Sh + ((size_t)b*M_PER_B + m0 + srow)*256 + k0 + sseg*8) = q0;
            CP_WAIT0();
        }
        __syncthreads();
    }

    // ---- epilogue: +c +mask, relu, row sums over 256 n, normalize ----
    const float* amb = am + b*256;
    float mv[2], rs[2];
    #pragma unroll
    for (int h = 0; h < 2; h++) {
        int mgl = m0 + mg*16 + h*8 + r;
        mv[h] = amb[mgl >> 8] * amb[mgl & 255];
        rs[h] = 0.f;
    }
    #pragma unroll
    for (int nt = 0; nt < 16; nt++) {
        float c0 = csm[ng*128 + nt*8 + q*2];
        float c1 = csm[ng*128 + nt*8 + q*2 + 1];
        float* a4 = acc + nt*4;
        float w0 = fmaxf(a4[0] + c0 + mv[0], 0.f);
        float w1 = fmaxf(a4[1] + c1 + mv[0], 0.f);
        float w2 = fmaxf(a4[2] + c0 + mv[1], 0.f);
        float w3 = fmaxf(a4[3] + c1 + mv[1], 0.f);
        a4[0] = w0; a4[1] = w1; a4[2] = w2; a4[3] = w3;
        rs[0] += w0 + w1; rs[1] += w2 + w3;
    }
    #pragma unroll
    for (int h = 0; h < 2; h++) {
        rs[h] += __shfl_xor_sync(0xffffffffu, rs[h], 1);
        rs[h] += __shfl_xor_sync(0xffffffffu, rs[h], 2);
    }
    if (q == 0) {
        rsum[ng*64 + mg*16 + r]     = rs[0];
        rsum[ng*64 + mg*16 + 8 + r] = rs[1];
    }
    __syncthreads();
    if (tid < 64) {
        float s = rsum[tid] + rsum[64 + tid];
        rsum[tid] = 1.f / (s + 2.56e-10f);   // sum(p + 1e-12) over 256
    }
    __syncthreads();
    {
        float inv0 = rsum[mg*16 + r];
        float inv1 = rsum[mg*16 + 8 + r];
        #pragma unroll
        for (int nt = 0; nt < 16; nt++) {
            acc[nt*4 + 0] *= inv0;
            acc[nt*4 + 1] *= inv0;
            acc[nt*4 + 2] *= inv1;
            acc[nt*4 + 3] *= inv1;
        }
    }

    // ---- transpose-stage (single round; sth fp16 [256 n][72 m]) ----
    __half* sth = (__half*)shc;
    #pragma unroll
    for (int nt = 0; nt < 16; nt++) {
        int n0 = ng*128 + nt*8 + q*2;
        int ml = mg*16 + r;
        sth[n0*72 + ml]           = __float2half(acc[nt*4 + 0]);
        sth[(n0 + 1)*72 + ml]     = __float2half(acc[nt*4 + 1]);
        sth[n0*72 + ml + 8]       = __float2half(acc[nt*4 + 2]);
        sth[(n0 + 1)*72 + ml + 8] = __float2half(acc[nt*4 + 3]);
    }
    __syncthreads();
    #pragma unroll
    for (int i = 0; i < 8; i++) {
        int idx = i*256 + tid;
        int n = idx >> 3, c = idx & 7;
        *(uint4*)(g_Ph + ((size_t)b*256 + n)*M_PER_B + m0 + c*8) =
            *(const uint4*)(shc + n*144 + c*16);
    }
}

// =====================================================================
// passB: G[n,h] partial = sum_m P^T[n,m] S[m,h]. CTA 128n x 128h, occ 2.
// grid x: (nt2*2 + ht), y: ks (split-K=32, 2048 m), z: b. 64 chunks of 32.
// =====================================================================
__global__ void __launch_bounds__(256, 2) passB_kernel()
{
    extern __shared__ char shc[];
    const uint32_t base_u = smem_u32(shc);

    const int tid = threadIdx.x, lane = tid & 31, w = tid >> 5;
    const int ngg = w >> 1, hg = w & 1;
    const int r = lane >> 2, q = lane & 3;
    const int nt2 = blockIdx.x >> 1, ht = blockIdx.x & 1;
    const int ks = blockIdx.y, b = blockIdx.z;

    const __half* Pb  = g_Ph + ((size_t)b*256 + nt2*128)*M_PER_B;
    const __half* Sbh = g_Sh + (size_t)b*M_PER_B*256;

    float acc[64];
    #pragma unroll
    for (int i = 0; i < 64; i++) acc[i] = 0.f;
    float tsum = 0.f;

    auto copy_chunk = [&](int ch, int stage) {
        int mb = ks*2048 + ch*32;
        uint32_t pd = base_u + stage*18944;
        #pragma unroll
        for (int i = 0; i < 2; i++) {
            int idx = i*256 + tid;
            int row = idx >> 2, c = idx & 3;
            cp16(pd + (uint32_t)row*80 + c*16, Pb + (size_t)row*M_PER_B + mb + c*8);
        }
        uint32_t sd = pd + 10240;
        #pragma unroll
        for (int i = 0; i < 2; i++) {
            int idx = i*256 + tid;
            int row = idx >> 4, c = idx & 15;
            cp16(sd + (uint32_t)row*272 + c*16, Sbh + (size_t)(mb + row)*256 + ht*128 + c*8);
        }
    };

    const uint32_t aOff = (uint32_t)(ngg*32 + (lane & 15))*80 + (lane >> 4)*16;
    const uint32_t bOff = 10240u + (uint32_t)(lane & 15)*272 + hg*128 + (lane >> 4)*16;

    copy_chunk(0, 0);
    CP_COMMIT();

    for (int ch = 0; ch < 64; ch++) {
        if (ch == 0) { CP_WAIT0(); __syncthreads(); }
        if (ch + 1 < 64) { copy_chunk(ch + 1, (ch + 1) & 1); CP_COMMIT(); }

        uint32_t sb = base_u + (ch & 1)*18944;
        if (ht == 0 && tid < 128) {
            const __half2* pr = (const __half2*)(shc + (ch & 1)*18944 + tid*80);
            #pragma unroll
            for (int j = 0; j < 16; j++) {
                float2 f = __half22float2(pr[j]);
                tsum += f.x + f.y;
            }
        }
        #pragma unroll
        for (int step = 0; step < 2; step++) {
            uint32_t af0[4], af1[4];
            ldm_x4(af0, sb + aOff + step*32);
            ldm_x4(af1, sb + aOff + 1280 + step*32);
            #pragma unroll
            for (int p = 0; p < 4; p++) {
                uint32_t bf[4];
                ldm_x4t(bf, sb + bOff + step*4352 + p*32);
                mma16(acc + (p*2)*4,        af0, bf[0], bf[1]);
                mma16(acc + 32 + (p*2)*4,   af1, bf[0], bf[1]);
                mma16(acc + (p*2+1)*4,      af0, bf[2], bf[3]);
                mma16(acc + 32 + (p*2+1)*4, af1, bf[2], bf[3]);
            }
        }
        if (ch + 1 < 64) { CP_WAIT0(); }
        __syncthreads();
    }

    // ---- stage + coalesced partial writes (2 rounds of 64 n rows) ----
    float* st = (float*)shc;   // [64][136]
    float* Wb = g_W + ((((size_t)b*KS_B + ks)*2 + nt2)*128)*256 + ht*128;
    for (int half = 0; half < 2; half++) {
        __syncthreads();
        if ((ngg >> 1) == half) {
            #pragma unroll
            for (int mt = 0; mt < 2; mt++)
                #pragma unroll
                for (int p = 0; p < 8; p++) {
                    int row0 = (ngg & 1)*32 + mt*16 + r;
                    int h0 = hg*64 + p*8 + q*2;
                    *(float2*)&st[row0*136 + h0] =
                        make_float2(acc[mt*32 + p*4 + 0], acc[mt*32 + p*4 + 1]);
                    *(float2*)&st[(row0 + 8)*136 + h0] =
                        make_float2(acc[mt*32 + p*4 + 2], acc[mt*32 + p*4 + 3]);
                }
        }
        __syncthreads();
        #pragma unroll
        for (int i = 0; i < 8; i++) {
            int idx = i*256 + tid;
            int rr = idx >> 5, c = (idx & 31) << 2;
            *(float4*)(Wb + (size_t)(half*64 + rr)*256 + c) = *(const float4*)&st[rr*136 + c];
        }
    }
    if (ht == 0 && tid < 128)
        g_Wt[(((size_t)b*KS_B + ks)*2 + nt2)*128 + tid] = tsum;
}

// =====================================================================
// reduce_kernel: G[b][n][h] = sum_ks g_W ; t[b][n] = sum_ks g_Wt.
// grid (256, 4), 256 threads; one block per (b, n) row.
// Reads 32 contiguous 1KB rows per block (coalesced, MLP 4).
// =====================================================================
__global__ void __launch_bounds__(256) reduce_kernel()
{
    int row = blockIdx.x, b = blockIdx.y, t = threadIdx.x;
    int nt = row >> 7, nl = row & 127;

    const size_t kstride = (size_t)2*128*256;
    const float* Wp = g_W + (((size_t)b*KS_B*2 + nt)*128 + nl)*256 + t;
    float a0 = 0.f, a1 = 0.f, a2 = 0.f, a3 = 0.f;
    #pragma unroll
    for (int ks = 0; ks < KS_B; ks += 4) {
        a0 += Wp[(size_t)ks*kstride];
        a1 += Wp[(size_t)(ks + 1)*kstride];
        a2 += Wp[(size_t)(ks + 2)*kstride];
        a3 += Wp[(size_t)(ks + 3)*kstride];
    }
    g_G[((size_t)b*256 + row)*256 + t] = (a0 + a1) + (a2 + a3);

    if (t < 32) {
        float v = g_Wt[(((size_t)b*KS_B + t)*2 + nt)*128 + nl];
        #pragma unroll
        for (int of = 16; of > 0; of >>= 1) v += __shfl_xor_sync(0xffffffffu, v, of);
        if (t == 0) g_T[b*256 + row] = v;
    }
}

// =====================================================================
// final_kernel: 4 n-rows per block. context = G@Wv + t*bv ;
//               out = context@Wo + bo ; y = LN(out + hidden)
// grid (64, 4), 256 threads.
// =====================================================================
__global__ void __launch_bounds__(256) final_kernel(
    const float* __restrict__ hidden,
    const float* __restrict__ Wv, const float* __restrict__ bv,
    const float* __restrict__ Wo, const float* __restrict__ bo,
    const float* __restrict__ gamma, const float* __restrict__ beta,
    float* __restrict__ out)
{
    int b = blockIdx.y, t = threadIdx.x;
    const int n0 = blockIdx.x * 4;
    __shared__ float grow[4][256];
    __shared__ float crow[4][256];
    __shared__ float wsum[4][8];

    #pragma unroll
    for (int j = 0; j < 4; j++)
        grow[j][t] = g_G[((size_t)b*256 + n0 + j)*256 + t];
    __syncthreads();

    float bvt = bv[t];
    float c0 = g_T[b*256 + n0]     * bvt;
    float c1 = g_T[b*256 + n0 + 1] * bvt;
    float c2 = g_T[b*256 + n0 + 2] * bvt;
    float c3 = g_T[b*256 + n0 + 3] * bvt;
    #pragma unroll 8
    for (int h = 0; h < 256; h++) {
        float wv = Wv[h*256 + t];
        c0 += grow[0][h] * wv;
        c1 += grow[1][h] * wv;
        c2 += grow[2][h] * wv;
        c3 += grow[3][h] * wv;
    }
    crow[0][t] = c0; crow[1][t] = c1; crow[2][t] = c2; crow[3][t] = c3;
    __syncthreads();

    float bot = bo[t];
    float o0 = bot, o1 = bot, o2 = bot, o3 = bot;
    #pragma unroll 8
    for (int d = 0; d < 256; d++) {
        float wo = Wo[d*256 + t];
        o0 += crow[0][d] * wo;
        o1 += crow[1][d] * wo;
        o2 += crow[2][d] * wo;
        o3 += crow[3][d] * wo;
    }
    float x[4];
    x[0] = o0 + hidden[(b*256 + n0)*256 + t];
    x[1] = o1 + hidden[(b*256 + n0 + 1)*256 + t];
    x[2] = o2 + hidden[(b*256 + n0 + 2)*256 + t];
    x[3] = o3 + hidden[(b*256 + n0 + 3)*256 + t];

    int lane = t & 31, w = t >> 5;
    float s[4] = {x[0], x[1], x[2], x[3]};
    #pragma unroll
    for (int of = 16; of > 0; of >>= 1)
        #pragma unroll
        for (int j = 0; j < 4; j++)
            s[j] += __shfl_xor_sync(0xffffffffu, s[j], of);
    if (lane == 0)
        #pragma unroll
        for (int j = 0; j < 4; j++) wsum[j][w] = s[j];
    __syncthreads();
    float dx[4];
    #pragma unroll
    for (int j = 0; j < 4; j++) {
        float tot = 0.f;
        #pragma unroll
        for (int i = 0; i < 8; i++) tot += wsum[j][i];
        dx[j] = x[j] - tot * (1.f/256.f);
        s[j] = dx[j] * dx[j];
    }
    __syncthreads();
    #pragma unroll
    for (int of = 16; of > 0; of >>= 1)
        #pragma unroll
        for (int j = 0; j < 4; j++)
            s[j] += __shfl_xor_sync(0xffffffffu, s[j], of);
    if (lane == 0)
        #pragma unroll
        for (int j = 0; j < 4; j++) wsum[j][w] = s[j];
    __syncthreads();

    float gm = gamma[t], bt = beta[t];
    #pragma unroll
    for (int j = 0; j < 4; j++) {
        float v = 0.f;
        #pragma unroll
        for (int i = 0; i < 8; i++) v += wsum[j][i];
        out[(b*256 + n0 + j)*256 + t] =
            gm * dx[j] * rsqrtf(v*(1.f/256.f) + 1e-5f) + bt;
    }
}

// =====================================================================
extern "C" void kernel_launch(void* const* d_in, const int* in_sizes, int n_in,
                              void* d_out, int out_size)
{
    const float* hidden = (const float*)d_in[0];
    const float* S      = (const float*)d_in[1];
    const float* am     = (const float*)d_in[2];
    const float* Wq     = (const float*)d_in[3];
    const float* bq     = (const float*)d_in[4];
    const float* Wk     = (const float*)d_in[5];
    const float* bk     = (const float*)d_in[6];
    const float* Wv     = (const float*)d_in[7];
    const float* bv     = (const float*)d_in[8];
    const float* Wo     = (const float*)d_in[9];
    const float* bo     = (const float*)d_in[10];
    const float* gamma  = (const float*)d_in[11];
    const float* beta   = (const float*)d_in[12];
    float* out          = (float*)d_out;

    const int smemA = 53248;   // 2x25600 stages + csm(1K) + rsum(512) ; sth 36864 overlays
    const int smemB = 38912;   // 2x18944 stages ; st f32 64x136 overlays
    cudaFuncSetAttribute(passA_kernel, cudaFuncAttributeMaxDynamicSharedMemorySize, smemA);
    cudaFuncSetAttribute(passB_kernel, cudaFuncAttributeMaxDynamicSharedMemorySize, smemB);

    prep_kernel<<<dim3(256, 4), 256>>>(hidden, Wq, bq, Wk, bk);
    passA_kernel<<<dim3(M_PER_B/64, 4), 256, smemA>>>(S, am);
    passB_kernel<<<dim3(4, KS_B, 4), 256, smemB>>>();
    reduce_kernel<<<dim3(256, 4), 256>>>();
    final_kernel<<<dim3(64, 4), 256>>>(hidden, Wv, bv, Wo, bo, gamma, beta, out);
}

// round 14
// speedup vs baseline: 1.0376x; 1.0376x over previous
#include <cuda_runtime.h>
#include <cuda_fp16.h>
#include <cstdint>

#define BB 4
#define M_PER_B 65536
#define KS_B 32

// ---- device scratch (static: allocation-free) ----
__device__ float  g_c[BB*256];                      // bq.k_n/16
__device__ __half g_Ah[BB*256*256];                 // A fp16 [b][n][h] (incl 1/16)
__device__ __half g_Sh[(size_t)BB*M_PER_B*256];     // S fp16 (written by passA)
__device__ __half g_Ph[(size_t)BB*256*M_PER_B];     // P^T fp16 [b][n][m]
__device__ float  g_W[(size_t)BB*KS_B*2*128*256];   // split-K partials of G (33.5 MB)
__device__ float  g_Wt[BB*KS_B*2*128];              // split-K partials of t[n]
__device__ float  g_G[BB*256*256];                  // reduced G [b][n][h] (1 MB)
__device__ float  g_T[BB*256];                      // reduced t [b][n]
__device__ float  g_Wvo[256*256];                   // Wv @ Wo
__device__ float  g_bvo[256];                       // bv @ Wo

// ---- helpers ----
__device__ __forceinline__ uint32_t smem_u32(const void* p) {
    return (uint32_t)__cvta_generic_to_shared(p);
}
__device__ __forceinline__ void cp16(uint32_t dst, const void* src) {
    asm volatile("cp.async.cg.shared.global [%0], [%1], 16;" :: "r"(dst), "l"(src));
}
#define CP_COMMIT() asm volatile("cp.async.commit_group;" ::: "memory")
#define CP_WAIT0()  asm volatile("cp.async.wait_group 0;" ::: "memory")

__device__ __forceinline__ uint32_t pack_h2(float lo, float hi) {
    uint32_t r;
    asm("cvt.rn.f16x2.f32 %0, %1, %2;" : "=r"(r) : "f"(hi), "f"(lo));
    return r;
}
__device__ __forceinline__ void ldm_x4(uint32_t* r, uint32_t addr) {
    asm volatile("ldmatrix.sync.aligned.m8n8.x4.shared.b16 {%0,%1,%2,%3}, [%4];"
        : "=r"(r[0]), "=r"(r[1]), "=r"(r[2]), "=r"(r[3]) : "r"(addr));
}
__device__ __forceinline__ void ldm_x4t(uint32_t* r, uint32_t addr) {
    asm volatile("ldmatrix.sync.aligned.m8n8.x4.trans.shared.b16 {%0,%1,%2,%3}, [%4];"
        : "=r"(r[0]), "=r"(r[1]), "=r"(r[2]), "=r"(r[3]) : "r"(addr));
}
__device__ __forceinline__ void mma16(float* d, const uint32_t* a,
                                      uint32_t b0, uint32_t b1) {
    asm volatile("mma.sync.aligned.m16n8k16.row.col.f32.f16.f16.f32 "
        "{%0,%1,%2,%3}, {%4,%5,%6,%7}, {%8,%9}, {%0,%1,%2,%3};"
        : "+f"(d[0]), "+f"(d[1]), "+f"(d[2]), "+f"(d[3])
        : "r"(a[0]), "r"(a[1]), "r"(a[2]), "r"(a[3]), "r"(b0), "r"(b1));
}

// =====================================================================
// Kernel 1: K = hidden@Wk + bk ; A fp16 [b][n][h] = (Wq[h,:].K[b,n,:])/16 ;
//           c[b][n] = (bq . K[b,n,:])/16
// =====================================================================
__global__ void __launch_bounds__(256) prep_kernel(
    const float* __restrict__ hidden,
    const float* __restrict__ Wq, const float* __restrict__ bq,
    const float* __restrict__ Wk, const float* __restrict__ bk)
{
    int n = blockIdx.x, b = blockIdx.y, t = threadIdx.x;
    __shared__ float hrow[256];
    __shared__ float krow[256];
    hrow[t] = hidden[(b*256 + n)*256 + t];
    __syncthreads();

    float a = bk[t];
    #pragma unroll 8
    for (int h = 0; h < 256; h++) a += hrow[h] * Wk[h*256 + t];
    krow[t] = a;
    __syncthreads();

    int lane = t & 31, w = t >> 5;
    const float sc = 0.0625f;
    for (int h = w; h < 256; h += 8) {
        float s = 0.f;
        #pragma unroll 4
        for (int d = lane; d < 256; d += 32) s += Wq[h*256 + d] * krow[d];
        #pragma unroll
        for (int of = 16; of > 0; of >>= 1) s += __shfl_xor_sync(0xffffffffu, s, of);
        if (lane == 0) g_Ah[(b*256 + n)*256 + h] = __float2half(s * sc);
    }
    if (w == 0) {
        float s = 0.f;
        #pragma unroll 4
        for (int d = lane; d < 256; d += 32) s += bq[d] * krow[d];
        #pragma unroll
        for (int of = 16; of > 0; of >>= 1) s += __shfl_xor_sync(0xffffffffu, s, of);
        if (lane == 0) g_c[b*256 + n] = s * sc;
    }
}

// =====================================================================
// Kernel 1b: Wvo[h][o] = sum_d Wv[h][d]*Wo[d][o] ; bvo[o] = sum_d bv[d]*Wo[d][o]
// grid 256 (one block per h-row), 256 threads (o = t).
// =====================================================================
__global__ void __launch_bounds__(256) prep2_kernel(
    const float* __restrict__ Wv, const float* __restrict__ bv,
    const float* __restrict__ Wo)
{
    int h = blockIdx.x, t = threadIdx.x;
    __shared__ float vrow[256];
    vrow[t] = Wv[h*256 + t];
    __syncthreads();

    float a = 0.f;
    #pragma unroll 8
    for (int d = 0; d < 256; d++) a += vrow[d] * Wo[d*256 + t];
    g_Wvo[h*256 + t] = a;

    if (h == 0) {
        __shared__ float brow[256];
        brow[t] = bv[t];
        __syncthreads();
        float s = 0.f;
        #pragma unroll 8
        for (int d = 0; d < 256; d++) s += brow[d] * Wo[d*256 + t];
        g_bvo[t] = s;
    }
}

// =====================================================================
// passA (round-10 proven config): CTA 64m x 256n, occ 2. fp16 mma +
// ldmatrix. K=256, 8 chunks of 32, double-buffered.
// =====================================================================
__global__ void __launch_bounds__(256, 2) passA_kernel(
    const float* __restrict__ S, const float* __restrict__ am)
{
    extern __shared__ char shc[];
    float* csm  = (float*)(shc + 51200);
    float* rsum = (float*)(shc + 52224);
    const uint32_t base_u = smem_u32(shc);

    const int tid = threadIdx.x, lane = tid & 31, w = tid >> 5;
    const int mg = w >> 1, ng = w & 1;
    const int r = lane >> 2, q = lane & 3;
    const int b = blockIdx.y;
    const int m0 = blockIdx.x * 64;

    csm[tid] = g_c[b*256 + tid];

    const float*  Sb  = S + ((size_t)b*M_PER_B + m0)*256;
    const __half* Abh = g_Ah + b*65536;

    float acc[64];
    #pragma unroll
    for (int i = 0; i < 64; i++) acc[i] = 0.f;

    const int srow = tid >> 2, sseg = tid & 3;
    float4 v0, v1;

    const uint32_t aOff = (uint32_t)(mg*16 + (lane & 15))*80 + (lane >> 4)*16;
    const uint32_t bOff = 5120u + (uint32_t)(ng*128 + (lane & 15))*80 + (lane >> 4)*16;

    // ---- chunk 0 preamble ----
    {
        const float4* sp = (const float4*)(Sb + (size_t)srow*256 + sseg*8);
        v0 = sp[0]; v1 = sp[1];
        uint32_t dst = base_u + 5120;
        #pragma unroll
        for (int i = 0; i < 4; i++) {
            int idx = i*256 + tid;
            int row = idx >> 2, c = idx & 3;
            cp16(dst + (uint32_t)row*80 + c*16, Abh + row*256 + c*8);
        }
        CP_COMMIT();
        uint4 q0 = make_uint4(pack_h2(v0.x, v0.y), pack_h2(v0.z, v0.w),
                              pack_h2(v1.x, v1.y), pack_h2(v1.z, v1.w));
        *(uint4*)(shc + srow*80 + sseg*16) = q0;
        *(uint4*)(g_Sh + ((size_t)b*M_PER_B + m0 + srow)*256 + sseg*8) = q0;
        CP_WAIT0();
        __syncthreads();
    }

    for (int kc = 0; kc < 8; kc++) {
        if (kc < 7) {
            int k0 = (kc + 1)*32;
            const float4* sp = (const float4*)(Sb + (size_t)srow*256 + k0 + sseg*8);
            v0 = sp[0]; v1 = sp[1];
            uint32_t dst = base_u + ((kc + 1) & 1)*25600 + 5120;
            #pragma unroll
            for (int i = 0; i < 4; i++) {
                int idx = i*256 + tid;
                int row = idx >> 2, c = idx & 3;
                cp16(dst + (uint32_t)row*80 + c*16, Abh + row*256 + k0 + c*8);
            }
            CP_COMMIT();
        }
        uint32_t sb = base_u + (kc & 1)*25600;
        #pragma unroll
        for (int step = 0; step < 2; step++) {
            uint32_t af[4];
            ldm_x4(af, sb + aOff + step*32);
            #pragma unroll
            for (int p = 0; p < 8; p++) {
                uint32_t bf[4];
                ldm_x4(bf, sb + bOff + p*1280 + step*32);
                mma16(acc + (p*2)*4,   af, bf[0], bf[2]);
                mma16(acc + (p*2+1)*4, af, bf[1], bf[3]);
            }
        }
        if (kc < 7) {
            int k0 = (kc + 1)*32;
            int stage = (kc + 1) & 1;
            uint4 q0 = make_uint4(pack_h2(v0.x, v0.y), pack_h2(v0.z, v0.w),
                                  pack_h2(v1.x, v1.y), pack_h2(v1.z, v1.w));
            *(uint4*)(shc + stage*25600 + srow*80 + sseg*16) = q0;
            *(uint4*)(g_Sh + ((size_t)b*M_PER_B + m0 + srow)*256 + k0 + sseg*8) = q0;
            CP_WAIT0();
        }
        __syncthreads();
    }

    // ---- epilogue: +c +mask, relu, row sums over 256 n, normalize ----
    const float* amb = am + b*256;
    float mv[2], rs[2];
    #pragma unroll
    for (int h = 0; h < 2; h++) {
        int mgl = m0 + mg*16 + h*8 + r;
        mv[h] = amb[mgl >> 8] * amb[mgl & 255];
        rs[h] = 0.f;
    }
    #pragma unroll
    for (int nt = 0; nt < 16; nt++) {
        float c0 = csm[ng*128 + nt*8 + q*2];
        float c1 = csm[ng*128 + nt*8 + q*2 + 1];
        float* a4 = acc + nt*4;
        float w0 = fmaxf(a4[0] + c0 + mv[0], 0.f);
        float w1 = fmaxf(a4[1] + c1 + mv[0], 0.f);
        float w2 = fmaxf(a4[2] + c0 + mv[1], 0.f);
        float w3 = fmaxf(a4[3] + c1 + mv[1], 0.f);
        a4[0] = w0; a4[1] = w1; a4[2] = w2; a4[3] = w3;
        rs[0] += w0 + w1; rs[1] += w2 + w3;
    }
    #pragma unroll
    for (int h = 0; h < 2; h++) {
        rs[h] += __shfl_xor_sync(0xffffffffu, rs[h], 1);
        rs[h] += __shfl_xor_sync(0xffffffffu, rs[h], 2);
    }
    if (q == 0) {
        rsum[ng*64 + mg*16 + r]     = rs[0];
        rsum[ng*64 + mg*16 + 8 + r] = rs[1];
    }
    __syncthreads();
    if (tid < 64) {
        float s = rsum[tid] + rsum[64 + tid];
        rsum[tid] = 1.f / (s + 2.56e-10f);   // sum(p + 1e-12) over 256
    }
    __syncthreads();
    {
        float inv0 = rsum[mg*16 + r];
        float inv1 = rsum[mg*16 + 8 + r];
        #pragma unroll
        for (int nt = 0; nt < 16; nt++) {
            acc[nt*4 + 0] *= inv0;
            acc[nt*4 + 1] *= inv0;
            acc[nt*4 + 2] *= inv1;
            acc[nt*4 + 3] *= inv1;
        }
    }

    // ---- transpose-stage (single round; sth fp16 [256 n][72 m]) ----
    __half* sth = (__half*)shc;
    #pragma unroll
    for (int nt = 0; nt < 16; nt++) {
        int n0 = ng*128 + nt*8 + q*2;
        int ml = mg*16 + r;
        sth[n0*72 + ml]           = __float2half(acc[nt*4 + 0]);
        sth[(n0 + 1)*72 + ml]     = __float2half(acc[nt*4 + 1]);
        sth[n0*72 + ml + 8]       = __float2half(acc[nt*4 + 2]);
        sth[(n0 + 1)*72 + ml + 8] = __float2half(acc[nt*4 + 3]);
    }
    __syncthreads();
    #pragma unroll
    for (int i = 0; i < 8; i++) {
        int idx = i*256 + tid;
        int n = idx >> 3, c = idx & 7;
        *(uint4*)(g_Ph + ((size_t)b*256 + n)*M_PER_B + m0 + c*8) =
            *(const uint4*)(shc + n*144 + c*16);
    }
}

// =====================================================================
// passB: G[n,h] partial = sum_m P^T[n,m] S[m,h]. CTA 128n x 128h, occ 2.
// grid x: (nt2*2 + ht), y: ks (split-K=32, 2048 m), z: b. 64 chunks of 32.
// =====================================================================
__global__ void __launch_bounds__(256, 2) passB_kernel()
{
    extern __shared__ char shc[];
    const uint32_t base_u = smem_u32(shc);

    const int tid = threadIdx.x, lane = tid & 31, w = tid >> 5;
    const int ngg = w >> 1, hg = w & 1;
    const int r = lane >> 2, q = lane & 3;
    const int nt2 = blockIdx.x >> 1, ht = blockIdx.x & 1;
    const int ks = blockIdx.y, b = blockIdx.z;

    const __half* Pb  = g_Ph + ((size_t)b*256 + nt2*128)*M_PER_B;
    const __half* Sbh = g_Sh + (size_t)b*M_PER_B*256;

    float acc[64];
    #pragma unroll
    for (int i = 0; i < 64; i++) acc[i] = 0.f;
    float tsum = 0.f;

    auto copy_chunk = [&](int ch, int stage) {
        int mb = ks*2048 + ch*32;
        uint32_t pd = base_u + stage*18944;
        #pragma unroll
        for (int i = 0; i < 2; i++) {
            int idx = i*256 + tid;
            int row = idx >> 2, c = idx & 3;
            cp16(pd + (uint32_t)row*80 + c*16, Pb + (size_t)row*M_PER_B + mb + c*8);
        }
        uint32_t sd = pd + 10240;
        #pragma unroll
        for (int i = 0; i < 2; i++) {
            int idx = i*256 + tid;
            int row = idx >> 4, c = idx & 15;
            cp16(sd + (uint32_t)row*272 + c*16, Sbh + (size_t)(mb + row)*256 + ht*128 + c*8);
        }
    };

    const uint32_t aOff = (uint32_t)(ngg*32 + (lane & 15))*80 + (lane >> 4)*16;
    const uint32_t bOff = 10240u + (uint32_t)(lane & 15)*272 + hg*128 + (lane >> 4)*16;

    copy_chunk(0, 0);
    CP_COMMIT();

    for (int ch = 0; ch < 64; ch++) {
        if (ch == 0) { CP_WAIT0(); __syncthreads(); }
        if (ch + 1 < 64) { copy_chunk(ch + 1, (ch + 1) & 1); CP_COMMIT(); }

        uint32_t sb = base_u + (ch & 1)*18944;
        if (ht == 0 && tid < 128) {
            const __half2* pr = (const __half2*)(shc + (ch & 1)*18944 + tid*80);
            #pragma unroll
            for (int j = 0; j < 16; j++) {
                float2 f = __half22float2(pr[j]);
                tsum += f.x + f.y;
            }
        }
        #pragma unroll
        for (int step = 0; step < 2; step++) {
            uint32_t af0[4], af1[4];
            ldm_x4(af0, sb + aOff + step*32);
            ldm_x4(af1, sb + aOff + 1280 + step*32);
            #pragma unroll
            for (int p = 0; p < 4; p++) {
                uint32_t bf[4];
                ldm_x4t(bf, sb + bOff + step*4352 + p*32);
                mma16(acc + (p*2)*4,        af0, bf[0], bf[1]);
                mma16(acc + 32 + (p*2)*4,   af1, bf[0], bf[1]);
                mma16(acc + (p*2+1)*4,      af0, bf[2], bf[3]);
                mma16(acc + 32 + (p*2+1)*4, af1, bf[2], bf[3]);
            }
        }
        if (ch + 1 < 64) { CP_WAIT0(); }
        __syncthreads();
    }

    // ---- stage + coalesced partial writes (2 rounds of 64 n rows) ----
    float* st = (float*)shc;   // [64][136]
    float* Wb = g_W + ((((size_t)b*KS_B + ks)*2 + nt2)*128)*256 + ht*128;
    for (int half = 0; half < 2; half++) {
        __syncthreads();
        if ((ngg >> 1) == half) {
            #pragma unroll
            for (int mt = 0; mt < 2; mt++)
                #pragma unroll
                for (int p = 0; p < 8; p++) {
                    int row0 = (ngg & 1)*32 + mt*16 + r;
                    int h0 = hg*64 + p*8 + q*2;
                    *(float2*)&st[row0*136 + h0] =
                        make_float2(acc[mt*32 + p*4 + 0], acc[mt*32 + p*4 + 1]);
                    *(float2*)&st[(row0 + 8)*136 + h0] =
                        make_float2(acc[mt*32 + p*4 + 2], acc[mt*32 + p*4 + 3]);
                }
        }
        __syncthreads();
        #pragma unroll
        for (int i = 0; i < 8; i++) {
            int idx = i*256 + tid;
            int rr = idx >> 5, c = (idx & 31) << 2;
            *(float4*)(Wb + (size_t)(half*64 + rr)*256 + c) = *(const float4*)&st[rr*136 + c];
        }
    }
    if (ht == 0 && tid < 128)
        g_Wt[(((size_t)b*KS_B + ks)*2 + nt2)*128 + tid] = tsum;
}

// =====================================================================
// reduce_kernel: G[b][n][h] = sum_ks g_W ; t[b][n] = sum_ks g_Wt.
// grid (256, 4), 256 threads; one block per (b, n) row.
// =====================================================================
__global__ void __launch_bounds__(256) reduce_kernel()
{
    int row = blockIdx.x, b = blockIdx.y, t = threadIdx.x;
    int nt = row >> 7, nl = row & 127;

    const size_t kstride = (size_t)2*128*256;
    const float* Wp = g_W + (((size_t)b*KS_B*2 + nt)*128 + nl)*256 + t;
    float a0 = 0.f, a1 = 0.f, a2 = 0.f, a3 = 0.f;
    #pragma unroll
    for (int ks = 0; ks < KS_B; ks += 4) {
        a0 += Wp[(size_t)ks*kstride];
        a1 += Wp[(size_t)(ks + 1)*kstride];
        a2 += Wp[(size_t)(ks + 2)*kstride];
        a3 += Wp[(size_t)(ks + 3)*kstride];
    }
    g_G[((size_t)b*256 + row)*256 + t] = (a0 + a1) + (a2 + a3);

    if (t < 32) {
        float v = g_Wt[(((size_t)b*KS_B + t)*2 + nt)*128 + nl];
        #pragma unroll
        for (int of = 16; of > 0; of >>= 1) v += __shfl_xor_sync(0xffffffffu, v, of);
        if (t == 0) g_T[b*256 + row] = v;
    }
}

// =====================================================================
// final_kernel: 2 n-rows per block, single fused GEMV.
//   out = G@Wvo + t*bvo + bo + hidden ; y = LN(out)
// grid (128, 4), 256 threads.
// =====================================================================
__global__ void __launch_bounds__(256) final_kernel(
    const float* __restrict__ hidden,
    const float* __restrict__ bo,
    const float* __restrict__ gamma, const float* __restrict__ beta,
    float* __restrict__ out)
{
    int b = blockIdx.y, t = threadIdx.x;
    const int n0 = blockIdx.x * 2;
    __shared__ float grow[2][256];
    __shared__ float wsum[2][8];

    grow[0][t] = g_G[((size_t)b*256 + n0)*256 + t];
    grow[1][t] = g_G[((size_t)b*256 + n0 + 1)*256 + t];
    __syncthreads();

    float bvot = g_bvo[t], bot = bo[t];
    float o0 = g_T[b*256 + n0]     * bvot + bot;
    float o1 = g_T[b*256 + n0 + 1] * bvot + bot;
    #pragma unroll 8
    for (int h = 0; h < 256; h++) {
        float wv = g_Wvo[h*256 + t];
        o0 += grow[0][h] * wv;
        o1 += grow[1][h] * wv;
    }
    float x0 = o0 + hidden[(b*256 + n0)*256 + t];
    float x1 = o1 + hidden[(b*256 + n0 + 1)*256 + t];

    int lane = t & 31, w = t >> 5;
    float s0 = x0, s1 = x1;
    #pragma unroll
    for (int of = 16; of > 0; of >>= 1) {
        s0 += __shfl_xor_sync(0xffffffffu, s0, of);
        s1 += __shfl_xor_sync(0xffffffffu, s1, of);
    }
    if (lane == 0) { wsum[0][w] = s0; wsum[1][w] = s1; }
    __syncthreads();
    float tot0 = 0.f, tot1 = 0.f;
    #pragma unroll
    for (int i = 0; i < 8; i++) { tot0 += wsum[0][i]; tot1 += wsum[1][i]; }
    float dx0 = x0 - tot0*(1.f/256.f);
    float dx1 = x1 - tot1*(1.f/256.f);
    __syncthreads();

    s0 = dx0*dx0; s1 = dx1*dx1;
    #pragma unroll
    for (int of = 16; of > 0; of >>= 1) {
        s0 += __shfl_xor_sync(0xffffffffu, s0, of);
        s1 += __shfl_xor_sync(0xffffffffu, s1, of);
    }
    if (lane == 0) { wsum[0][w] = s0; wsum[1][w] = s1; }
    __syncthreads();
    float v0 = 0.f, v1 = 0.f;
    #pragma unroll
    for (int i = 0; i < 8; i++) { v0 += wsum[0][i]; v1 += wsum[1][i]; }

    float gm = gamma[t], bt = beta[t];
    out[(b*256 + n0)*256 + t]     = gm * dx0 * rsqrtf(v0*(1.f/256.f) + 1e-5f) + bt;
    out[(b*256 + n0 + 1)*256 + t] = gm * dx1 * rsqrtf(v1*(1.f/256.f) + 1e-5f) + bt;
}

// =====================================================================
extern "C" void kernel_launch(void* const* d_in, const int* in_sizes, int n_in,
                              void* d_out, int out_size)
{
    const float* hidden = (const float*)d_in[0];
    const float* S      = (const float*)d_in[1];
    const float* am     = (const float*)d_in[2];
    const float* Wq     = (const float*)d_in[3];
    const float* bq     = (const float*)d_in[4];
    const float* Wk     = (const float*)d_in[5];
    const float* bk     = (const float*)d_in[6];
    const float* Wv     = (const float*)d_in[7];
    const float* bv     = (const float*)d_in[8];
    const float* Wo     = (const float*)d_in[9];
    const float* bo     = (const float*)d_in[10];
    const float* gamma  = (const float*)d_in[11];
    const float* beta   = (const float*)d_in[12];
    float* out          = (float*)d_out;

    const int smemA = 53248;   // 2x25600 stages + csm(1K) + rsum(512) ; sth 36864 overlays
    const int smemB = 38912;   // 2x18944 stages ; st f32 64x136 overlays
    cudaFuncSetAttribute(passA_kernel, cudaFuncAttributeMaxDynamicSharedMemorySize, smemA);
    cudaFuncSetAttribute(passB_kernel, cudaFuncAttributeMaxDynamicSharedMemorySize, smemB);

    prep_kernel<<<dim3(256, 4), 256>>>(hidden, Wq, bq, Wk, bk);
    prep2_kernel<<<256, 256>>>(Wv, bv, Wo);
    passA_kernel<<<dim3(M_PER_B/64, 4), 256, smemA>>>(S, am);
    passB_kernel<<<dim3(4, KS_B, 4), 256, smemB>>>();
    reduce_kernel<<<dim3(256, 4), 256>>>();
    final_kernel<<<dim3(128, 4), 256>>>(hidden, bo, gamma, beta, out);
}

// round 15
// speedup vs baseline: 1.1435x; 1.1021x over previous
#include <cuda_runtime.h>
#include <cuda_fp16.h>
#include <cstdint>

#define BB 4
#define M_PER_B 65536
#define KS_B 32

// ---- device scratch (static: allocation-free) ----
__device__ float  g_c[BB*256];                      // bq.k_n/16
__device__ __half g_Ah[BB*256*256];                 // A fp16 [b][n][h] (incl 1/16)
__device__ __half g_Sh[(size_t)BB*M_PER_B*256];     // S fp16 (written by passA)
__device__ __half g_Ph[(size_t)BB*256*M_PER_B];     // P^T fp16 [b][n][m]
__device__ float  g_W[(size_t)BB*KS_B*2*128*256];   // split-K partials of G (33.5 MB)
__device__ float  g_Wt[BB*KS_B*2*128];              // split-K partials of t[n]
__device__ float  g_G[BB*256*256];                  // reduced G [b][n][h] (1 MB)
__device__ float  g_T[BB*256];                      // reduced t [b][n]
__device__ float  g_Wvo[256*256];                   // Wv @ Wo
__device__ float  g_bvo[256];                       // bv @ Wo

// ---- helpers ----
__device__ __forceinline__ uint32_t smem_u32(const void* p) {
    return (uint32_t)__cvta_generic_to_shared(p);
}
__device__ __forceinline__ void cp16(uint32_t dst, const void* src) {
    asm volatile("cp.async.cg.shared.global [%0], [%1], 16;" :: "r"(dst), "l"(src));
}
#define CP_COMMIT() asm volatile("cp.async.commit_group;" ::: "memory")
#define CP_WAIT0()  asm volatile("cp.async.wait_group 0;" ::: "memory")

__device__ __forceinline__ uint32_t pack_h2(float lo, float hi) {
    uint32_t r;
    asm("cvt.rn.f16x2.f32 %0, %1, %2;" : "=r"(r) : "f"(hi), "f"(lo));
    return r;
}
__device__ __forceinline__ void ldm_x4(uint32_t* r, uint32_t addr) {
    asm volatile("ldmatrix.sync.aligned.m8n8.x4.shared.b16 {%0,%1,%2,%3}, [%4];"
        : "=r"(r[0]), "=r"(r[1]), "=r"(r[2]), "=r"(r[3]) : "r"(addr));
}
__device__ __forceinline__ void ldm_x4t(uint32_t* r, uint32_t addr) {
    asm volatile("ldmatrix.sync.aligned.m8n8.x4.trans.shared.b16 {%0,%1,%2,%3}, [%4];"
        : "=r"(r[0]), "=r"(r[1]), "=r"(r[2]), "=r"(r[3]) : "r"(addr));
}
__device__ __forceinline__ void mma16(float* d, const uint32_t* a,
                                      uint32_t b0, uint32_t b1) {
    asm volatile("mma.sync.aligned.m16n8k16.row.col.f32.f16.f16.f32 "
        "{%0,%1,%2,%3}, {%4,%5,%6,%7}, {%8,%9}, {%0,%1,%2,%3};"
        : "+f"(d[0]), "+f"(d[1]), "+f"(d[2]), "+f"(d[3])
        : "r"(a[0]), "r"(a[1]), "r"(a[2]), "r"(a[3]), "r"(b0), "r"(b1));
}

// =====================================================================
// Kernel 1 (fused): blocks n<256: K = hidden@Wk + bk ; A fp16 ; c.
//                   blocks n>=256: Wvo row h=(n-256)*4+b ; bvo (n==256,b==0).
// grid (320, 4), 256 threads.
// =====================================================================
__global__ void __launch_bounds__(256) prep_kernel(
    const float* __restrict__ hidden,
    const float* __restrict__ Wq, const float* __restrict__ bq,
    const float* __restrict__ Wk, const float* __restrict__ bk,
    const float* __restrict__ Wv, const float* __restrict__ bv,
    const float* __restrict__ Wo)
{
    int n = blockIdx.x, b = blockIdx.y, t = threadIdx.x;
    __shared__ float hrow[256];
    __shared__ float krow[256];

    if (n >= 256) {
        int h = (n - 256)*4 + b;
        hrow[t] = Wv[h*256 + t];
        __syncthreads();
        float a = 0.f;
        #pragma unroll 8
        for (int d = 0; d < 256; d++) a += hrow[d] * Wo[d*256 + t];
        g_Wvo[h*256 + t] = a;
        if (h == 0) {
            krow[t] = bv[t];
            __syncthreads();
            float s = 0.f;
            #pragma unroll 8
            for (int d = 0; d < 256; d++) s += krow[d] * Wo[d*256 + t];
            g_bvo[t] = s;
        }
        return;
    }

    hrow[t] = hidden[(b*256 + n)*256 + t];
    __syncthreads();

    float a = bk[t];
    #pragma unroll 8
    for (int h = 0; h < 256; h++) a += hrow[h] * Wk[h*256 + t];
    krow[t] = a;
    __syncthreads();

    int lane = t & 31, w = t >> 5;
    const float sc = 0.0625f;
    for (int h = w; h < 256; h += 8) {
        float s = 0.f;
        #pragma unroll 4
        for (int d = lane; d < 256; d += 32) s += Wq[h*256 + d] * krow[d];
        #pragma unroll
        for (int of = 16; of > 0; of >>= 1) s += __shfl_xor_sync(0xffffffffu, s, of);
        if (lane == 0) g_Ah[(b*256 + n)*256 + h] = __float2half(s * sc);
    }
    if (w == 0) {
        float s = 0.f;
        #pragma unroll 4
        for (int d = lane; d < 256; d += 32) s += bq[d] * krow[d];
        #pragma unroll
        for (int of = 16; of > 0; of >>= 1) s += __shfl_xor_sync(0xffffffffu, s, of);
        if (lane == 0) g_c[b*256 + n] = s * sc;
    }
}

// =====================================================================
// passA (round-10 proven config, FROZEN): CTA 64m x 256n, occ 2.
// fp16 mma + ldmatrix. K=256, 8 chunks of 32, double-buffered.
// =====================================================================
__global__ void __launch_bounds__(256, 2) passA_kernel(
    const float* __restrict__ S, const float* __restrict__ am)
{
    extern __shared__ char shc[];
    float* csm  = (float*)(shc + 51200);
    float* rsum = (float*)(shc + 52224);
    const uint32_t base_u = smem_u32(shc);

    const int tid = threadIdx.x, lane = tid & 31, w = tid >> 5;
    const int mg = w >> 1, ng = w & 1;
    const int r = lane >> 2, q = lane & 3;
    const int b = blockIdx.y;
    const int m0 = blockIdx.x * 64;

    csm[tid] = g_c[b*256 + tid];

    const float*  Sb  = S + ((size_t)b*M_PER_B + m0)*256;
    const __half* Abh = g_Ah + b*65536;

    float acc[64];
    #pragma unroll
    for (int i = 0; i < 64; i++) acc[i] = 0.f;

    const int srow = tid >> 2, sseg = tid & 3;
    float4 v0, v1;

    const uint32_t aOff = (uint32_t)(mg*16 + (lane & 15))*80 + (lane >> 4)*16;
    const uint32_t bOff = 5120u + (uint32_t)(ng*128 + (lane & 15))*80 + (lane >> 4)*16;

    // ---- chunk 0 preamble ----
    {
        const float4* sp = (const float4*)(Sb + (size_t)srow*256 + sseg*8);
        v0 = sp[0]; v1 = sp[1];
        uint32_t dst = base_u + 5120;
        #pragma unroll
        for (int i = 0; i < 4; i++) {
            int idx = i*256 + tid;
            int row = idx >> 2, c = idx & 3;
            cp16(dst + (uint32_t)row*80 + c*16, Abh + row*256 + c*8);
        }
        CP_COMMIT();
        uint4 q0 = make_uint4(pack_h2(v0.x, v0.y), pack_h2(v0.z, v0.w),
                              pack_h2(v1.x, v1.y), pack_h2(v1.z, v1.w));
        *(uint4*)(shc + srow*80 + sseg*16) = q0;
        *(uint4*)(g_Sh + ((size_t)b*M_PER_B + m0 + srow)*256 + sseg*8) = q0;
        CP_WAIT0();
        __syncthreads();
    }

    for (int kc = 0; kc < 8; kc++) {
        if (kc < 7) {
            int k0 = (kc + 1)*32;
            const float4* sp = (const float4*)(Sb + (size_t)srow*256 + k0 + sseg*8);
            v0 = sp[0]; v1 = sp[1];
            uint32_t dst = base_u + ((kc + 1) & 1)*25600 + 5120;
            #pragma unroll
            for (int i = 0; i < 4; i++) {
                int idx = i*256 + tid;
                int row = idx >> 2, c = idx & 3;
                cp16(dst + (uint32_t)row*80 + c*16, Abh + row*256 + k0 + c*8);
            }
            CP_COMMIT();
        }
        uint32_t sb = base_u + (kc & 1)*25600;
        #pragma unroll
        for (int step = 0; step < 2; step++) {
            uint32_t af[4];
            ldm_x4(af, sb + aOff + step*32);
            #pragma unroll
            for (int p = 0; p < 8; p++) {
                uint32_t bf[4];
                ldm_x4(bf, sb + bOff + p*1280 + step*32);
                mma16(acc + (p*2)*4,   af, bf[0], bf[2]);
                mma16(acc + (p*2+1)*4, af, bf[1], bf[3]);
            }
        }
        if (kc < 7) {
            int k0 = (kc + 1)*32;
            int stage = (kc + 1) & 1;
            uint4 q0 = make_uint4(pack_h2(v0.x, v0.y), pack_h2(v0.z, v0.w),
                                  pack_h2(v1.x, v1.y), pack_h2(v1.z, v1.w));
            *(uint4*)(shc + stage*25600 + srow*80 + sseg*16) = q0;
            *(uint4*)(g_Sh + ((size_t)b*M_PER_B + m0 + srow)*256 + k0 + sseg*8) = q0;
            CP_WAIT0();
        }
        __syncthreads();
    }

    // ---- epilogue: +c +mask, relu, row sums over 256 n, normalize ----
    const float* amb = am + b*256;
    float mv[2], rs[2];
    #pragma unroll
    for (int h = 0; h < 2; h++) {
        int mgl = m0 + mg*16 + h*8 + r;
        mv[h] = amb[mgl >> 8] * amb[mgl & 255];
        rs[h] = 0.f;
    }
    #pragma unroll
    for (int nt = 0; nt < 16; nt++) {
        float c0 = csm[ng*128 + nt*8 + q*2];
        float c1 = csm[ng*128 + nt*8 + q*2 + 1];
        float* a4 = acc + nt*4;
        float w0 = fmaxf(a4[0] + c0 + mv[0], 0.f);
        float w1 = fmaxf(a4[1] + c1 + mv[0], 0.f);
        float w2 = fmaxf(a4[2] + c0 + mv[1], 0.f);
        float w3 = fmaxf(a4[3] + c1 + mv[1], 0.f);
        a4[0] = w0; a4[1] = w1; a4[2] = w2; a4[3] = w3;
        rs[0] += w0 + w1; rs[1] += w2 + w3;
    }
    #pragma unroll
    for (int h = 0; h < 2; h++) {
        rs[h] += __shfl_xor_sync(0xffffffffu, rs[h], 1);
        rs[h] += __shfl_xor_sync(0xffffffffu, rs[h], 2);
    }
    if (q == 0) {
        rsum[ng*64 + mg*16 + r]     = rs[0];
        rsum[ng*64 + mg*16 + 8 + r] = rs[1];
    }
    __syncthreads();
    if (tid < 64) {
        float s = rsum[tid] + rsum[64 + tid];
        rsum[tid] = 1.f / (s + 2.56e-10f);   // sum(p + 1e-12) over 256
    }
    __syncthreads();
    {
        float inv0 = rsum[mg*16 + r];
        float inv1 = rsum[mg*16 + 8 + r];
        #pragma unroll
        for (int nt = 0; nt < 16; nt++) {
            acc[nt*4 + 0] *= inv0;
            acc[nt*4 + 1] *= inv0;
            acc[nt*4 + 2] *= inv1;
            acc[nt*4 + 3] *= inv1;
        }
    }

    // ---- transpose-stage (single round; sth fp16 [256 n][72 m]) ----
    __half* sth = (__half*)shc;
    #pragma unroll
    for (int nt = 0; nt < 16; nt++) {
        int n0 = ng*128 + nt*8 + q*2;
        int ml = mg*16 + r;
        sth[n0*72 + ml]           = __float2half(acc[nt*4 + 0]);
        sth[(n0 + 1)*72 + ml]     = __float2half(acc[nt*4 + 1]);
        sth[n0*72 + ml + 8]       = __float2half(acc[nt*4 + 2]);
        sth[(n0 + 1)*72 + ml + 8] = __float2half(acc[nt*4 + 3]);
    }
    __syncthreads();
    #pragma unroll
    for (int i = 0; i < 8; i++) {
        int idx = i*256 + tid;
        int n = idx >> 3, c = idx & 7;
        *(uint4*)(g_Ph + ((size_t)b*256 + n)*M_PER_B + m0 + c*8) =
            *(const uint4*)(shc + n*144 + c*16);
    }
}

// =====================================================================
// passB: G[n,h] partial = sum_m P^T[n,m] S[m,h]. CTA 128n x 128h, occ 2.
// grid x: (nt2*2 + ht), y: ks (split-K=32, 2048 m), z: b.
// 32 chunks of 64 m (halved barrier count vs 64x32).
// smem bytes: stage s @ s*35840: Ph fp16[128 n][64 m pad72] (18432)
//             + Ss fp16[64 m][128 h pad136] (17408).
// staging st f32[64][136] (34816) overlays.
// =====================================================================
__global__ void __launch_bounds__(256, 2) passB_kernel()
{
    extern __shared__ char shc[];
    const uint32_t base_u = smem_u32(shc);

    const int tid = threadIdx.x, lane = tid & 31, w = tid >> 5;
    const int ngg = w >> 1, hg = w & 1;
    const int r = lane >> 2, q = lane & 3;
    const int nt2 = blockIdx.x >> 1, ht = blockIdx.x & 1;
    const int ks = blockIdx.y, b = blockIdx.z;

    const __half* Pb  = g_Ph + ((size_t)b*256 + nt2*128)*M_PER_B;
    const __half* Sbh = g_Sh + (size_t)b*M_PER_B*256;

    float acc[64];
    #pragma unroll
    for (int i = 0; i < 64; i++) acc[i] = 0.f;
    float tsum = 0.f;

    auto copy_chunk = [&](int ch, int stage) {
        int mb = ks*2048 + ch*64;
        uint32_t pd = base_u + stage*35840;
        #pragma unroll
        for (int i = 0; i < 4; i++) {
            int idx = i*256 + tid;
            int row = idx >> 3, c = idx & 7;
            cp16(pd + (uint32_t)row*144 + c*16, Pb + (size_t)row*M_PER_B + mb + c*8);
        }
        uint32_t sd = pd + 18432;
        #pragma unroll
        for (int i = 0; i < 4; i++) {
            int idx = i*256 + tid;
            int row = idx >> 4, c = idx & 15;
            cp16(sd + (uint32_t)row*272 + c*16, Sbh + (size_t)(mb + row)*256 + ht*128 + c*8);
        }
    };

    const uint32_t aOff = (uint32_t)(ngg*32 + (lane & 15))*144 + (lane >> 4)*16;
    const uint32_t bOff = 18432u + (uint32_t)(lane & 15)*272 + hg*128 + (lane >> 4)*16;

    copy_chunk(0, 0);
    CP_COMMIT();

    for (int ch = 0; ch < 32; ch++) {
        if (ch == 0) { CP_WAIT0(); __syncthreads(); }
        if (ch + 1 < 32) { copy_chunk(ch + 1, (ch + 1) & 1); CP_COMMIT(); }

        uint32_t sb = base_u + (ch & 1)*35840;
        if (ht == 0 && tid < 128) {
            const __half2* pr = (const __half2*)(shc + (ch & 1)*35840 + tid*144);
            #pragma unroll
            for (int j = 0; j < 32; j++) {
                float2 f = __half22float2(pr[j]);
                tsum += f.x + f.y;
            }
        }
        #pragma unroll
        for (int step = 0; step < 4; step++) {
            uint32_t af0[4], af1[4];
            ldm_x4(af0, sb + aOff + step*32);
            ldm_x4(af1, sb + aOff + 2304 + step*32);
            #pragma unroll
            for (int p = 0; p < 4; p++) {
                uint32_t bf[4];
                ldm_x4t(bf, sb + bOff + step*4352 + p*32);
                mma16(acc + (p*2)*4,        af0, bf[0], bf[1]);
                mma16(acc + 32 + (p*2)*4,   af1, bf[0], bf[1]);
                mma16(acc + (p*2+1)*4,      af0, bf[2], bf[3]);
                mma16(acc + 32 + (p*2+1)*4, af1, bf[2], bf[3]);
            }
        }
        if (ch + 1 < 32) { CP_WAIT0(); }
        __syncthreads();
    }

    // ---- stage + coalesced partial writes (2 rounds of 64 n rows) ----
    float* st = (float*)shc;   // [64][136]
    float* Wb = g_W + ((((size_t)b*KS_B + ks)*2 + nt2)*128)*256 + ht*128;
    for (int half = 0; half < 2; half++) {
        __syncthreads();
        if ((ngg >> 1) == half) {
            #pragma unroll
            for (int mt = 0; mt < 2; mt++)
                #pragma unroll
                for (int p = 0; p < 8; p++) {
                    int row0 = (ngg & 1)*32 + mt*16 + r;
                    int h0 = hg*64 + p*8 + q*2;
                    *(float2*)&st[row0*136 + h0] =
                        make_float2(acc[mt*32 + p*4 + 0], acc[mt*32 + p*4 + 1]);
                    *(float2*)&st[(row0 + 8)*136 + h0] =
                        make_float2(acc[mt*32 + p*4 + 2], acc[mt*32 + p*4 + 3]);
                }
        }
        __syncthreads();
        #pragma unroll
        for (int i = 0; i < 8; i++) {
            int idx = i*256 + tid;
            int rr = idx >> 5, c = (idx & 31) << 2;
            *(float4*)(Wb + (size_t)(half*64 + rr)*256 + c) = *(const float4*)&st[rr*136 + c];
        }
    }
    if (ht == 0 && tid < 128)
        g_Wt[(((size_t)b*KS_B + ks)*2 + nt2)*128 + tid] = tsum;
}

// =====================================================================
// reduce_kernel: G[b][n][h] = sum_ks g_W ; t[b][n] = sum_ks g_Wt.
// grid (256, 4), 256 threads; one block per (b, n) row.
// =====================================================================
__global__ void __launch_bounds__(256) reduce_kernel()
{
    int row = blockIdx.x, b = blockIdx.y, t = threadIdx.x;
    int nt = row >> 7, nl = row & 127;

    const size_t kstride = (size_t)2*128*256;
    const float* Wp = g_W + (((size_t)b*KS_B*2 + nt)*128 + nl)*256 + t;
    float a0 = 0.f, a1 = 0.f, a2 = 0.f, a3 = 0.f;
    #pragma unroll
    for (int ks = 0; ks < KS_B; ks += 4) {
        a0 += Wp[(size_t)ks*kstride];
        a1 += Wp[(size_t)(ks + 1)*kstride];
        a2 += Wp[(size_t)(ks + 2)*kstride];
        a3 += Wp[(size_t)(ks + 3)*kstride];
    }
    g_G[((size_t)b*256 + row)*256 + t] = (a0 + a1) + (a2 + a3);

    if (t < 32) {
        float v = g_Wt[(((size_t)b*KS_B + t)*2 + nt)*128 + nl];
        #pragma unroll
        for (int of = 16; of > 0; of >>= 1) v += __shfl_xor_sync(0xffffffffu, v, of);
        if (t == 0) g_T[b*256 + row] = v;
    }
}

// =====================================================================
// final_kernel: 2 n-rows per block, single fused GEMV.
//   out = G@Wvo + t*bvo + bo + hidden ; y = LN(out)
// grid (128, 4), 256 threads.
// =====================================================================
__global__ void __launch_bounds__(256) final_kernel(
    const float* __restrict__ hidden,
    const float* __restrict__ bo,
    const float* __restrict__ gamma, const float* __restrict__ beta,
    float* __restrict__ out)
{
    int b = blockIdx.y, t = threadIdx.x;
    const int n0 = blockIdx.x * 2;
    __shared__ float grow[2][256];
    __shared__ float wsum[2][8];

    grow[0][t] = g_G[((size_t)b*256 + n0)*256 + t];
    grow[1][t] = g_G[((size_t)b*256 + n0 + 1)*256 + t];
    __syncthreads();

    float bvot = g_bvo[t], bot = bo[t];
    float o0 = g_T[b*256 + n0]     * bvot + bot;
    float o1 = g_T[b*256 + n0 + 1] * bvot + bot;
    #pragma unroll 8
    for (int h = 0; h < 256; h++) {
        float wv = g_Wvo[h*256 + t];
        o0 += grow[0][h] * wv;
        o1 += grow[1][h] * wv;
    }
    float x0 = o0 + hidden[(b*256 + n0)*256 + t];
    float x1 = o1 + hidden[(b*256 + n0 + 1)*256 + t];

    int lane = t & 31, w = t >> 5;
    float s0 = x0, s1 = x1;
    #pragma unroll
    for (int of = 16; of > 0; of >>= 1) {
        s0 += __shfl_xor_sync(0xffffffffu, s0, of);
        s1 += __shfl_xor_sync(0xffffffffu, s1, of);
    }
    if (lane == 0) { wsum[0][w] = s0; wsum[1][w] = s1; }
    __syncthreads();
    float tot0 = 0.f, tot1 = 0.f;
    #pragma unroll
    for (int i = 0; i < 8; i++) { tot0 += wsum[0][i]; tot1 += wsum[1][i]; }
    float dx0 = x0 - tot0*(1.f/256.f);
    float dx1 = x1 - tot1*(1.f/256.f);
    __syncthreads();

    s0 = dx0*dx0; s1 = dx1*dx1;
    #pragma unroll
    for (int of = 16; of > 0; of >>= 1) {
        s0 += __shfl_xor_sync(0xffffffffu, s0, of);
        s1 += __shfl_xor_sync(0xffffffffu, s1, of);
    }
    if (lane == 0) { wsum[0][w] = s0; wsum[1][w] = s1; }
    __syncthreads();
    float v0 = 0.f, v1 = 0.f;
    #pragma unroll
    for (int i = 0; i < 8; i++) { v0 += wsum[0][i]; v1 += wsum[1][i]; }

    float gm = gamma[t], bt = beta[t];
    out[(b*256 + n0)*256 + t]     = gm * dx0 * rsqrtf(v0*(1.f/256.f) + 1e-5f) + bt;
    out[(b*256 + n0 + 1)*256 + t] = gm * dx1 * rsqrtf(v1*(1.f/256.f) + 1e-5f) + bt;
}

// =====================================================================
extern "C" void kernel_launch(void* const* d_in, const int* in_sizes, int n_in,
                              void* d_out, int out_size)
{
    const float* hidden = (const float*)d_in[0];
    const float* S      = (const float*)d_in[1];
    const float* am     = (const float*)d_in[2];
    const float* Wq     = (const float*)d_in[3];
    const float* bq     = (const float*)d_in[4];
    const float* Wk     = (const float*)d_in[5];
    const float* bk     = (const float*)d_in[6];
    const float* Wv     = (const float*)d_in[7];
    const float* bv     = (const float*)d_in[8];
    const float* Wo     = (const float*)d_in[9];
    const float* bo     = (const float*)d_in[10];
    const float* gamma  = (const float*)d_in[11];
    const float* beta   = (const float*)d_in[12];
    float* out          = (float*)d_out;

    const int smemA = 53248;   // 2x25600 stages + csm(1K) + rsum(512) ; sth 36864 overlays
    const int smemB = 71680;   // 2x35840 stages ; st f32 64x136 (34816) overlays
    cudaFuncSetAttribute(passA_kernel, cudaFuncAttributeMaxDynamicSharedMemorySize, smemA);
    cudaFuncSetAttribute(passB_kernel, cudaFuncAttributeMaxDynamicSharedMemorySize, smemB);

    prep_kernel<<<dim3(320, 4), 256>>>(hidden, Wq, bq, Wk, bk, Wv, bv, Wo);
    passA_kernel<<<dim3(M_PER_B/64, 4), 256, smemA>>>(S, am);
    passB_kernel<<<dim3(4, KS_B, 4), 256, smemB>>>();
    reduce_kernel<<<dim3(256, 4), 256>>>();
    final_kernel<<<dim3(128, 4), 256>>>(hidden, bo, gamma, beta, out);
}

// round 16
// speedup vs baseline: 1.1616x; 1.0159x over previous
#include <cuda_runtime.h>
#include <cuda_fp16.h>
#include <cstdint>

#define BB 4
#define M_PER_B 65536
#define KS_B 32

// ---- device scratch (static: allocation-free) ----
__device__ float  g_c[BB*256];                      // bq.k_n/16
__device__ __half g_Ah[BB*256*256];                 // A fp16 [b][n][h] (incl 1/16)
__device__ __half g_Sh[(size_t)BB*M_PER_B*256];     // S fp16 (written by passA)
__device__ __half g_Ph[(size_t)BB*256*M_PER_B];     // P^T fp16 [b][n][m]
__device__ float  g_W[(size_t)BB*KS_B*2*128*256];   // split-K partials of G (33.5 MB)
__device__ float  g_Wt[BB*KS_B*2*128];              // split-K partials of t[n]
__device__ float  g_G[BB*256*256];                  // reduced G [b][n][h] (1 MB)
__device__ float  g_T[BB*256];                      // reduced t [b][n]
__device__ float  g_Wvo[256*256];                   // Wv @ Wo
__device__ float  g_bvo[256];                       // bv @ Wo

// ---- helpers ----
__device__ __forceinline__ uint32_t smem_u32(const void* p) {
    return (uint32_t)__cvta_generic_to_shared(p);
}
__device__ __forceinline__ void cp16(uint32_t dst, const void* src) {
    asm volatile("cp.async.cg.shared.global [%0], [%1], 16;" :: "r"(dst), "l"(src));
}
#define CP_COMMIT() asm volatile("cp.async.commit_group;" ::: "memory")
#define CP_WAIT0()  asm volatile("cp.async.wait_group 0;" ::: "memory")

__device__ __forceinline__ uint32_t pack_h2(float lo, float hi) {
    uint32_t r;
    asm("cvt.rn.f16x2.f32 %0, %1, %2;" : "=r"(r) : "f"(hi), "f"(lo));
    return r;
}
__device__ __forceinline__ void ldm_x4(uint32_t* r, uint32_t addr) {
    asm volatile("ldmatrix.sync.aligned.m8n8.x4.shared.b16 {%0,%1,%2,%3}, [%4];"
        : "=r"(r[0]), "=r"(r[1]), "=r"(r[2]), "=r"(r[3]) : "r"(addr));
}
__device__ __forceinline__ void ldm_x4t(uint32_t* r, uint32_t addr) {
    asm volatile("ldmatrix.sync.aligned.m8n8.x4.trans.shared.b16 {%0,%1,%2,%3}, [%4];"
        : "=r"(r[0]), "=r"(r[1]), "=r"(r[2]), "=r"(r[3]) : "r"(addr));
}
__device__ __forceinline__ void mma16(float* d, const uint32_t* a,
                                      uint32_t b0, uint32_t b1) {
    asm volatile("mma.sync.aligned.m16n8k16.row.col.f32.f16.f16.f32 "
        "{%0,%1,%2,%3}, {%4,%5,%6,%7}, {%8,%9}, {%0,%1,%2,%3};"
        : "+f"(d[0]), "+f"(d[1]), "+f"(d[2]), "+f"(d[3])
        : "r"(a[0]), "r"(a[1]), "r"(a[2]), "r"(a[3]), "r"(b0), "r"(b1));
}

// =====================================================================
// Kernel 1 (fused): blocks n<256: K = hidden@Wk + bk ; A fp16 ; c.
//                   blocks n>=256: Wvo row h=(n-256)*4+b ; bvo (n==256,b==0).
// grid (320, 4), 256 threads.
// =====================================================================
__global__ void __launch_bounds__(256) prep_kernel(
    const float* __restrict__ hidden,
    const float* __restrict__ Wq, const float* __restrict__ bq,
    const float* __restrict__ Wk, const float* __restrict__ bk,
    const float* __restrict__ Wv, const float* __restrict__ bv,
    const float* __restrict__ Wo)
{
    int n = blockIdx.x, b = blockIdx.y, t = threadIdx.x;
    __shared__ float hrow[256];
    __shared__ float krow[256];

    if (n >= 256) {
        int h = (n - 256)*4 + b;
        hrow[t] = Wv[h*256 + t];
        __syncthreads();
        float a = 0.f;
        #pragma unroll 8
        for (int d = 0; d < 256; d++) a += hrow[d] * Wo[d*256 + t];
        g_Wvo[h*256 + t] = a;
        if (h == 0) {
            krow[t] = bv[t];
            __syncthreads();
            float s = 0.f;
            #pragma unroll 8
            for (int d = 0; d < 256; d++) s += krow[d] * Wo[d*256 + t];
            g_bvo[t] = s;
        }
        return;
    }

    hrow[t] = hidden[(b*256 + n)*256 + t];
    __syncthreads();

    float a = bk[t];
    #pragma unroll 8
    for (int h = 0; h < 256; h++) a += hrow[h] * Wk[h*256 + t];
    krow[t] = a;
    __syncthreads();

    int lane = t & 31, w = t >> 5;
    const float sc = 0.0625f;
    for (int h = w; h < 256; h += 8) {
        float s = 0.f;
        #pragma unroll 4
        for (int d = lane; d < 256; d += 32) s += Wq[h*256 + d] * krow[d];
        #pragma unroll
        for (int of = 16; of > 0; of >>= 1) s += __shfl_xor_sync(0xffffffffu, s, of);
        if (lane == 0) g_Ah[(b*256 + n)*256 + h] = __float2half(s * sc);
    }
    if (w == 0) {
        float s = 0.f;
        #pragma unroll 4
        for (int d = lane; d < 256; d += 32) s += bq[d] * krow[d];
        #pragma unroll
        for (int of = 16; of > 0; of >>= 1) s += __shfl_xor_sync(0xffffffffu, s, of);
        if (lane == 0) g_c[b*256 + n] = s * sc;
    }
}

// =====================================================================
// passA: CTA 64m x 256n, occ 2. fp16 mma + ldmatrix.
// K=256 in 4 chunks of 64 (halved barrier count), double-buffered.
// Warps: 4 m-groups(16) x 2 n-groups(128).
// smem bytes: stage s @ s*46080: Sh fp16[64][72] (9216) + Ah fp16[256][72]
//   (36864). csm f32 @92160, rsum @93184. staging sth fp16[256][72] overlays.
// =====================================================================
__global__ void __launch_bounds__(256, 2) passA_kernel(
    const float* __restrict__ S, const float* __restrict__ am)
{
    extern __shared__ char shc[];
    float* csm  = (float*)(shc + 92160);
    float* rsum = (float*)(shc + 93184);
    const uint32_t base_u = smem_u32(shc);

    const int tid = threadIdx.x, lane = tid & 31, w = tid >> 5;
    const int mg = w >> 1, ng = w & 1;
    const int r = lane >> 2, q = lane & 3;
    const int b = blockIdx.y;
    const int m0 = blockIdx.x * 64;

    csm[tid] = g_c[b*256 + tid];

    const float*  Sb  = S + ((size_t)b*M_PER_B + m0)*256;
    const __half* Abh = g_Ah + b*65536;

    float acc[64];
    #pragma unroll
    for (int i = 0; i < 64; i++) acc[i] = 0.f;

    const int srow = tid >> 2, sseg = tid & 3;   // 64 rows, 4 thr/row, 16 f32 each
    float4 v0, v1, v2, v3;

    const uint32_t aOff = (uint32_t)(mg*16 + (lane & 15))*144 + (lane >> 4)*16;
    const uint32_t bOff = 9216u + (uint32_t)(ng*128 + (lane & 15))*144 + (lane >> 4)*16;

    // ---- chunk 0 preamble ----
    {
        const float4* sp = (const float4*)(Sb + (size_t)srow*256 + sseg*16);
        v0 = sp[0]; v1 = sp[1]; v2 = sp[2]; v3 = sp[3];
        uint32_t dst = base_u + 9216;
        #pragma unroll
        for (int i = 0; i < 8; i++) {
            int idx = i*256 + tid;
            int row = idx >> 3, c = idx & 7;
            cp16(dst + (uint32_t)row*144 + c*16, Abh + row*256 + c*8);
        }
        CP_COMMIT();
        uint4 q0 = make_uint4(pack_h2(v0.x, v0.y), pack_h2(v0.z, v0.w),
                              pack_h2(v1.x, v1.y), pack_h2(v1.z, v1.w));
        uint4 q1 = make_uint4(pack_h2(v2.x, v2.y), pack_h2(v2.z, v2.w),
                              pack_h2(v3.x, v3.y), pack_h2(v3.z, v3.w));
        *(uint4*)(shc + srow*144 + sseg*32)      = q0;
        *(uint4*)(shc + srow*144 + sseg*32 + 16) = q1;
        uint4* gp = (uint4*)(g_Sh + ((size_t)b*M_PER_B + m0 + srow)*256 + sseg*16);
        gp[0] = q0; gp[1] = q1;
        CP_WAIT0();
        __syncthreads();
    }

    for (int kc = 0; kc < 4; kc++) {
        if (kc < 3) {
            int k0 = (kc + 1)*64;
            const float4* sp = (const float4*)(Sb + (size_t)srow*256 + k0 + sseg*16);
            v0 = sp[0]; v1 = sp[1]; v2 = sp[2]; v3 = sp[3];
            uint32_t dst = base_u + ((kc + 1) & 1)*46080 + 9216;
            #pragma unroll
            for (int i = 0; i < 8; i++) {
                int idx = i*256 + tid;
                int row = idx >> 3, c = idx & 7;
                cp16(dst + (uint32_t)row*144 + c*16, Abh + row*256 + k0 + c*8);
            }
            CP_COMMIT();
        }
        uint32_t sb = base_u + (kc & 1)*46080;
        #pragma unroll
        for (int step = 0; step < 4; step++) {
            uint32_t af[4];
            ldm_x4(af, sb + aOff + step*32);
            #pragma unroll
            for (int p = 0; p < 8; p++) {
                uint32_t bf[4];
                ldm_x4(bf, sb + bOff + p*2304 + step*32);
                mma16(acc + (p*2)*4,   af, bf[0], bf[2]);
                mma16(acc + (p*2+1)*4, af, bf[1], bf[3]);
            }
        }
        if (kc < 3) {
            int k0 = (kc + 1)*64;
            int stage = (kc + 1) & 1;
            uint4 q0 = make_uint4(pack_h2(v0.x, v0.y), pack_h2(v0.z, v0.w),
                                  pack_h2(v1.x, v1.y), pack_h2(v1.z, v1.w));
            uint4 q1 = make_uint4(pack_h2(v2.x, v2.y), pack_h2(v2.z, v2.w),
                                  pack_h2(v3.x, v3.y), pack_h2(v3.z, v3.w));
            *(uint4*)(shc + stage*46080 + srow*144 + sseg*32)      = q0;
            *(uint4*)(shc + stage*46080 + srow*144 + sseg*32 + 16) = q1;
            uint4* gp = (uint4*)(g_Sh + ((size_t)b*M_PER_B + m0 + srow)*256 + k0 + sseg*16);
            gp[0] = q0; gp[1] = q1;
            CP_WAIT0();
        }
        __syncthreads();
    }

    // ---- epilogue: +c +mask, relu, row sums over 256 n, normalize ----
    const float* amb = am + b*256;
    float mv[2], rs[2];
    #pragma unroll
    for (int h = 0; h < 2; h++) {
        int mgl = m0 + mg*16 + h*8 + r;
        mv[h] = amb[mgl >> 8] * amb[mgl & 255];
        rs[h] = 0.f;
    }
    #pragma unroll
    for (int nt = 0; nt < 16; nt++) {
        float c0 = csm[ng*128 + nt*8 + q*2];
        float c1 = csm[ng*128 + nt*8 + q*2 + 1];
        float* a4 = acc + nt*4;
        float w0 = fmaxf(a4[0] + c0 + mv[0], 0.f);
        float w1 = fmaxf(a4[1] + c1 + mv[0], 0.f);
        float w2 = fmaxf(a4[2] + c0 + mv[1], 0.f);
        float w3 = fmaxf(a4[3] + c1 + mv[1], 0.f);
        a4[0] = w0; a4[1] = w1; a4[2] = w2; a4[3] = w3;
        rs[0] += w0 + w1; rs[1] += w2 + w3;
    }
    #pragma unroll
    for (int h = 0; h < 2; h++) {
        rs[h] += __shfl_xor_sync(0xffffffffu, rs[h], 1);
        rs[h] += __shfl_xor_sync(0xffffffffu, rs[h], 2);
    }
    if (q == 0) {
        rsum[ng*64 + mg*16 + r]     = rs[0];
        rsum[ng*64 + mg*16 + 8 + r] = rs[1];
    }
    __syncthreads();
    if (tid < 64) {
        float s = rsum[tid] + rsum[64 + tid];
        rsum[tid] = 1.f / (s + 2.56e-10f);   // sum(p + 1e-12) over 256
    }
    __syncthreads();
    {
        float inv0 = rsum[mg*16 + r];
        float inv1 = rsum[mg*16 + 8 + r];
        #pragma unroll
        for (int nt = 0; nt < 16; nt++) {
            acc[nt*4 + 0] *= inv0;
            acc[nt*4 + 1] *= inv0;
            acc[nt*4 + 2] *= inv1;
            acc[nt*4 + 3] *= inv1;
        }
    }

    // ---- transpose-stage (single round; sth fp16 [256 n][72 m]) ----
    __half* sth = (__half*)shc;
    #pragma unroll
    for (int nt = 0; nt < 16; nt++) {
        int n0 = ng*128 + nt*8 + q*2;
        int ml = mg*16 + r;
        sth[n0*72 + ml]           = __float2half(acc[nt*4 + 0]);
        sth[(n0 + 1)*72 + ml]     = __float2half(acc[nt*4 + 1]);
        sth[n0*72 + ml + 8]       = __float2half(acc[nt*4 + 2]);
        sth[(n0 + 1)*72 + ml + 8] = __float2half(acc[nt*4 + 3]);
    }
    __syncthreads();
    #pragma unroll
    for (int i = 0; i < 8; i++) {
        int idx = i*256 + tid;
        int n = idx >> 3, c = idx & 7;
        *(uint4*)(g_Ph + ((size_t)b*256 + n)*M_PER_B + m0 + c*8) =
            *(const uint4*)(shc + n*144 + c*16);
    }
}

// =====================================================================
// passB (round-15 proven config, FROZEN): CTA 128n x 128h, occ 2.
// 32 chunks of 64 m, double-buffered.
// =====================================================================
__global__ void __launch_bounds__(256, 2) passB_kernel()
{
    extern __shared__ char shc[];
    const uint32_t base_u = smem_u32(shc);

    const int tid = threadIdx.x, lane = tid & 31, w = tid >> 5;
    const int ngg = w >> 1, hg = w & 1;
    const int r = lane >> 2, q = lane & 3;
    const int nt2 = blockIdx.x >> 1, ht = blockIdx.x & 1;
    const int ks = blockIdx.y, b = blockIdx.z;

    const __half* Pb  = g_Ph + ((size_t)b*256 + nt2*128)*M_PER_B;
    const __half* Sbh = g_Sh + (size_t)b*M_PER_B*256;

    float acc[64];
    #pragma unroll
    for (int i = 0; i < 64; i++) acc[i] = 0.f;
    float tsum = 0.f;

    auto copy_chunk = [&](int ch, int stage) {
        int mb = ks*2048 + ch*64;
        uint32_t pd = base_u + stage*35840;
        #pragma unroll
        for (int i = 0; i < 4; i++) {
            int idx = i*256 + tid;
            int row = idx >> 3, c = idx & 7;
            cp16(pd + (uint32_t)row*144 + c*16, Pb + (size_t)row*M_PER_B + mb + c*8);
        }
        uint32_t sd = pd + 18432;
        #pragma unroll
        for (int i = 0; i < 4; i++) {
            int idx = i*256 + tid;
            int row = idx >> 4, c = idx & 15;
            cp16(sd + (uint32_t)row*272 + c*16, Sbh + (size_t)(mb + row)*256 + ht*128 + c*8);
        }
    };

    const uint32_t aOff = (uint32_t)(ngg*32 + (lane & 15))*144 + (lane >> 4)*16;
    const uint32_t bOff = 18432u + (uint32_t)(lane & 15)*272 + hg*128 + (lane >> 4)*16;

    copy_chunk(0, 0);
    CP_COMMIT();

    for (int ch = 0; ch < 32; ch++) {
        if (ch == 0) { CP_WAIT0(); __syncthreads(); }
        if (ch + 1 < 32) { copy_chunk(ch + 1, (ch + 1) & 1); CP_COMMIT(); }

        uint32_t sb = base_u + (ch & 1)*35840;
        if (ht == 0 && tid < 128) {
            const __half2* pr = (const __half2*)(shc + (ch & 1)*35840 + tid*144);
            #pragma unroll
            for (int j = 0; j < 32; j++) {
                float2 f = __half22float2(pr[j]);
                tsum += f.x + f.y;
            }
        }
        #pragma unroll
        for (int step = 0; step < 4; step++) {
            uint32_t af0[4], af1[4];
            ldm_x4(af0, sb + aOff + step*32);
            ldm_x4(af1, sb + aOff + 2304 + step*32);
            #pragma unroll
            for (int p = 0; p < 4; p++) {
                uint32_t bf[4];
                ldm_x4t(bf, sb + bOff + step*4352 + p*32);
                mma16(acc + (p*2)*4,        af0, bf[0], bf[1]);
                mma16(acc + 32 + (p*2)*4,   af1, bf[0], bf[1]);
                mma16(acc + (p*2+1)*4,      af0, bf[2], bf[3]);
                mma16(acc + 32 + (p*2+1)*4, af1, bf[2], bf[3]);
            }
        }
        if (ch + 1 < 32) { CP_WAIT0(); }
        __syncthreads();
    }

    // ---- stage + coalesced partial writes (2 rounds of 64 n rows) ----
    float* st = (float*)shc;   // [64][136]
    float* Wb = g_W + ((((size_t)b*KS_B + ks)*2 + nt2)*128)*256 + ht*128;
    for (int half = 0; half < 2; half++) {
        __syncthreads();
        if ((ngg >> 1) == half) {
            #pragma unroll
            for (int mt = 0; mt < 2; mt++)
                #pragma unroll
                for (int p = 0; p < 8; p++) {
                    int row0 = (ngg & 1)*32 + mt*16 + r;
                    int h0 = hg*64 + p*8 + q*2;
                    *(float2*)&st[row0*136 + h0] =
                        make_float2(acc[mt*32 + p*4 + 0], acc[mt*32 + p*4 + 1]);
                    *(float2*)&st[(row0 + 8)*136 + h0] =
                        make_float2(acc[mt*32 + p*4 + 2], acc[mt*32 + p*4 + 3]);
                }
        }
        __syncthreads();
        #pragma unroll
        for (int i = 0; i < 8; i++) {
            int idx = i*256 + tid;
            int rr = idx >> 5, c = (idx & 31) << 2;
            *(float4*)(Wb + (size_t)(half*64 + rr)*256 + c) = *(const float4*)&st[rr*136 + c];
        }
    }
    if (ht == 0 && tid < 128)
        g_Wt[(((size_t)b*KS_B + ks)*2 + nt2)*128 + tid] = tsum;
}

// =====================================================================
// reduce_kernel: G[b][n][h] = sum_ks g_W ; t[b][n] = sum_ks g_Wt.
// grid (256, 4), 256 threads; one block per (b, n) row.
// =====================================================================
__global__ void __launch_bounds__(256) reduce_kernel()
{
    int row = blockIdx.x, b = blockIdx.y, t = threadIdx.x;
    int nt = row >> 7, nl = row & 127;

    const size_t kstride = (size_t)2*128*256;
    const float* Wp = g_W + (((size_t)b*KS_B*2 + nt)*128 + nl)*256 + t;
    float a0 = 0.f, a1 = 0.f, a2 = 0.f, a3 = 0.f;
    #pragma unroll
    for (int ks = 0; ks < KS_B; ks += 4) {
        a0 += Wp[(size_t)ks*kstride];
        a1 += Wp[(size_t)(ks + 1)*kstride];
        a2 += Wp[(size_t)(ks + 2)*kstride];
        a3 += Wp[(size_t)(ks + 3)*kstride];
    }
    g_G[((size_t)b*256 + row)*256 + t] = (a0 + a1) + (a2 + a3);

    if (t < 32) {
        float v = g_Wt[(((size_t)b*KS_B + t)*2 + nt)*128 + nl];
        #pragma unroll
        for (int of = 16; of > 0; of >>= 1) v += __shfl_xor_sync(0xffffffffu, v, of);
        if (t == 0) g_T[b*256 + row] = v;
    }
}

// =====================================================================
// final_kernel: 2 n-rows per block, single fused GEMV.
//   out = G@Wvo + t*bvo + bo + hidden ; y = LN(out)
// grid (128, 4), 256 threads.
// =====================================================================
__global__ void __launch_bounds__(256) final_kernel(
    const float* __restrict__ hidden,
    const float* __restrict__ bo,
    const float* __restrict__ gamma, const float* __restrict__ beta,
    float* __restrict__ out)
{
    int b = blockIdx.y, t = threadIdx.x;
    const int n0 = blockIdx.x * 2;
    __shared__ float grow[2][256];
    __shared__ float wsum[2][8];

    grow[0][t] = g_G[((size_t)b*256 + n0)*256 + t];
    grow[1][t] = g_G[((size_t)b*256 + n0 + 1)*256 + t];
    __syncthreads();

    float bvot = g_bvo[t], bot = bo[t];
    float o0 = g_T[b*256 + n0]     * bvot + bot;
    float o1 = g_T[b*256 + n0 + 1] * bvot + bot;
    #pragma unroll 8
    for (int h = 0; h < 256; h++) {
        float wv = g_Wvo[h*256 + t];
        o0 += grow[0][h] * wv;
        o1 += grow[1][h] * wv;
    }
    float x0 = o0 + hidden[(b*256 + n0)*256 + t];
    float x1 = o1 + hidden[(b*256 + n0 + 1)*256 + t];

    int lane = t & 31, w = t >> 5;
    float s0 = x0, s1 = x1;
    #pragma unroll
    for (int of = 16; of > 0; of >>= 1) {
        s0 += __shfl_xor_sync(0xffffffffu, s0, of);
        s1 += __shfl_xor_sync(0xffffffffu, s1, of);
    }
    if (lane == 0) { wsum[0][w] = s0; wsum[1][w] = s1; }
    __syncthreads();
    float tot0 = 0.f, tot1 = 0.f;
    #pragma unroll
    for (int i = 0; i < 8; i++) { tot0 += wsum[0][i]; tot1 += wsum[1][i]; }
    float dx0 = x0 - tot0*(1.f/256.f);
    float dx1 = x1 - tot1*(1.f/256.f);
    __syncthreads();

    s0 = dx0*dx0; s1 = dx1*dx1;
    #pragma unroll
    for (int of = 16; of > 0; of >>= 1) {
        s0 += __shfl_xor_sync(0xffffffffu, s0, of);
        s1 += __shfl_xor_sync(0xffffffffu, s1, of);
    }
    if (lane == 0) { wsum[0][w] = s0; wsum[1][w] = s1; }
    __syncthreads();
    float v0 = 0.f, v1 = 0.f;
    #pragma unroll
    for (int i = 0; i < 8; i++) { v0 += wsum[0][i]; v1 += wsum[1][i]; }

    float gm = gamma[t], bt = beta[t];
    out[(b*256 + n0)*256 + t]     = gm * dx0 * rsqrtf(v0*(1.f/256.f) + 1e-5f) + bt;
    out[(b*256 + n0 + 1)*256 + t] = gm * dx1 * rsqrtf(v1*(1.f/256.f) + 1e-5f) + bt;
}

// =====================================================================
extern "C" void kernel_launch(void* const* d_in, const int* in_sizes, int n_in,
                              void* d_out, int out_size)
{
    const float* hidden = (const float*)d_in[0];
    const float* S      = (const float*)d_in[1];
    const float* am     = (const float*)d_in[2];
    const float* Wq     = (const float*)d_in[3];
    const float* bq     = (const float*)d_in[4];
    const float* Wk     = (const float*)d_in[5];
    const float* bk     = (const float*)d_in[6];
    const float* Wv     = (const float*)d_in[7];
    const float* bv     = (const float*)d_in[8];
    const float* Wo     = (const float*)d_in[9];
    const float* bo     = (const float*)d_in[10];
    const float* gamma  = (const float*)d_in[11];
    const float* beta   = (const float*)d_in[12];
    float* out          = (float*)d_out;

    const int smemA = 93696;   // 2x46080 stages + csm(1K) + rsum(512) ; sth 36864 overlays
    const int smemB = 71680;   // 2x35840 stages ; st f32 64x136 (34816) overlays
    cudaFuncSetAttribute(passA_kernel, cudaFuncAttributeMaxDynamicSharedMemorySize, smemA);
    cudaFuncSetAttribute(passB_kernel, cudaFuncAttributeMaxDynamicSharedMemorySize, smemB);

    prep_kernel<<<dim3(320, 4), 256>>>(hidden, Wq, bq, Wk, bk, Wv, bv, Wo);
    passA_kernel<<<dim3(M_PER_B/64, 4), 256, smemA>>>(S, am);
    passB_kernel<<<dim3(4, KS_B, 4), 256, smemB>>>();
    reduce_kernel<<<dim3(256, 4), 256>>>();
    final_kernel<<<dim3(128, 4), 256>>>(hidden, bo, gamma, beta, out);
}